// round 6
// baseline (speedup 1.0000x reference)
#include <cuda_runtime.h>
#include <math.h>

#define NN 10000
#define EE 160000

typedef unsigned long long ull;

// ---------------- packed f32x2 helpers (FFMA2 path, PTX-only) ----------------
__device__ __forceinline__ ull pk2(float x) {
    ull r; asm("mov.b64 %0, {%1, %1};" : "=l"(r) : "f"(x)); return r;
}
__device__ __forceinline__ void fma2(ull& d, ull a, ull b) {
    asm("fma.rn.f32x2 %0, %1, %2, %3;" : "=l"(d) : "l"(a), "l"(b), "l"(d));
}
__device__ __forceinline__ float2 up2(ull v) {
    float2 r; asm("mov.b64 {%0, %1}, %2;" : "=f"(r.x), "=f"(r.y) : "l"(v)); return r;
}

// ---------------- static scratch ----------------
__device__ float g_y[NN * 512];              // y_s at [n*512+w]; y_v[c] at [n*512+128+c*128+w]
__device__ float g_h[EE * 64];               // MLP hidden (after layer 2)
__device__ float g_w[(size_t)EE * 512];      // MLP output (ss|sv|vs|vv each 128)
__device__ float g_acc[NN * 1024];           // s(256) | v[c](256)x3
__device__ int   g_cnt[NN];
__device__ int   g_cur[NN];
__device__ int   g_rs[NN + 1];
__device__ int   g_perm[EE];

// ---------------- zero counters ----------------
__global__ void k_zero() {
    int i = blockIdx.x * blockDim.x + threadIdx.x;
    if (i < NN) { g_cnt[i] = 0; g_cur[i] = 0; }
}

// ---------------- lin1: y = x @ W * 1/sqrt(128) ----------------
__global__ __launch_bounds__(256) void k_lin1(const float* __restrict__ nf,
                                              const float* __restrict__ ws,
                                              const float* __restrict__ wv) {
    const int ch = blockIdx.z;            // 0: scalar, 1..3: vector channel
    const int m0 = blockIdx.x * 64;
    const float* W = (ch == 0) ? ws : wv;
    __shared__ float As[64][33];
    __shared__ __align__(16) float Bs[32][128];
    const int tid = threadIdx.x;
    const int tx = tid & 15, ty = tid >> 4;
    ull acc2[4][4] = {};                  // 4 rows x 4 packed pairs (8 cols)
    for (int k0 = 0; k0 < 128; k0 += 32) {
        for (int idx = tid; idx < 64 * 32; idx += 256) {
            int m = idx >> 5, k = idx & 31;
            int n = m0 + m;
            float v = 0.f;
            if (n < NN) {
                int u = k0 + k;
                v = (ch == 0) ? nf[n * 512 + u] : nf[n * 512 + 128 + u * 3 + (ch - 1)];
            }
            As[m][k] = v;
        }
        for (int idx = tid; idx < 32 * 128; idx += 256) {
            int k = idx >> 7, w = idx & 127;
            Bs[k][w] = W[(k0 + k) * 128 + w];
        }
        __syncthreads();
        #pragma unroll
        for (int k = 0; k < 32; k++) {
            const ull* bp = reinterpret_cast<const ull*>(&Bs[k][tx * 8]);
            ull bb[4] = {bp[0], bp[1], bp[2], bp[3]};
            #pragma unroll
            for (int i = 0; i < 4; i++) {
                ull aa = pk2(As[ty * 4 + i][k]);
                #pragma unroll
                for (int j = 0; j < 4; j++) fma2(acc2[i][j], aa, bb[j]);
            }
        }
        __syncthreads();
    }
    const float L1 = 0.08838834764831845f;   // 1/sqrt(128)
    #pragma unroll
    for (int i = 0; i < 4; i++) {
        int n = m0 + ty * 4 + i;
        if (n >= NN) continue;
        #pragma unroll
        for (int j = 0; j < 4; j++) {
            float2 p = up2(acc2[i][j]);
            int w = tx * 8 + j * 2;
            float v0 = p.x * L1, v1 = p.y * L1;
            if (ch == 0) { g_y[n * 512 + w] = v0; g_y[n * 512 + w + 1] = v1; }
            else {
                g_y[n * 512 + 128 + (ch - 1) * 128 + w]     = v0;
                g_y[n * 512 + 128 + (ch - 1) * 128 + w + 1] = v1;
            }
        }
    }
}

// ---------------- edge MLP layers 1-2 ----------------
__global__ __launch_bounds__(256) void k_mlp12(const float* __restrict__ ef,
                                               const float* __restrict__ w0,
                                               const float* __restrict__ w1) {
    __shared__ float sw0[8 * 64];
    __shared__ float sw1[64 * 64];
    __shared__ float sef[32 * 8];
    __shared__ float sh1[32 * 64];
    const int tid = threadIdx.x;
    const int e0 = blockIdx.x * 32;
    for (int i = tid; i < 512; i += 256) sw0[i] = w0[i];
    for (int i = tid; i < 4096; i += 256) sw1[i] = w1[i];
    sef[tid] = ef[e0 * 8 + tid];
    __syncthreads();
    for (int idx = tid; idx < 2048; idx += 256) {
        int e = idx >> 6, j = idx & 63;
        float t = 0.f;
        #pragma unroll
        for (int k = 0; k < 8; k++) t += sef[e * 8 + k] * sw0[k * 64 + j];
        t *= 0.35355339059327373f;                       // 1/sqrt(8)
        sh1[idx] = 1.679f * t / (1.f + expf(-t));
    }
    __syncthreads();
    for (int idx = tid; idx < 2048; idx += 256) {
        int e = idx >> 6, j = idx & 63;
        float t = 0.f;
        #pragma unroll 8
        for (int k = 0; k < 64; k++) t += sh1[e * 64 + k] * sw1[k * 64 + j];
        t *= 0.125f;
        g_h[(e0 + e) * 64 + j] = 1.679f * t / (1.f + expf(-t));
    }
}

// ---------------- edge MLP layer 3: g_w = g_h @ w2 / 8 ----------------
__global__ __launch_bounds__(256) void k_mlp3(const float* __restrict__ w2) {
    const int e0 = blockIdx.x * 64;
    const int c0 = blockIdx.y * 128;
    __shared__ float As[64][33];
    __shared__ __align__(16) float Bs[32][128];
    const int tid = threadIdx.x;
    const int tx = tid & 15, ty = tid >> 4;
    ull acc2[4][4] = {};
    for (int k0 = 0; k0 < 64; k0 += 32) {
        for (int idx = tid; idx < 64 * 32; idx += 256) {
            int m = idx >> 5, k = idx & 31;
            As[m][k] = g_h[(e0 + m) * 64 + k0 + k];
        }
        for (int idx = tid; idx < 32 * 128; idx += 256) {
            int k = idx >> 7, w = idx & 127;
            Bs[k][w] = w2[(k0 + k) * 512 + c0 + w];
        }
        __syncthreads();
        #pragma unroll
        for (int k = 0; k < 32; k++) {
            const ull* bp = reinterpret_cast<const ull*>(&Bs[k][tx * 8]);
            ull bb[4] = {bp[0], bp[1], bp[2], bp[3]};
            #pragma unroll
            for (int i = 0; i < 4; i++) {
                ull aa = pk2(As[ty * 4 + i][k]);
                #pragma unroll
                for (int j = 0; j < 4; j++) fma2(acc2[i][j], aa, bb[j]);
            }
        }
        __syncthreads();
    }
    #pragma unroll
    for (int i = 0; i < 4; i++) {
        size_t row = (size_t)(e0 + ty * 4 + i) * 512 + c0;
        #pragma unroll
        for (int j = 0; j < 4; j++) {
            float2 p = up2(acc2[i][j]);
            g_w[row + tx * 8 + j * 2]     = p.x * 0.125f;
            g_w[row + tx * 8 + j * 2 + 1] = p.y * 0.125f;
        }
    }
}

// ---------------- CSR build ----------------
__global__ void k_hist(const int* __restrict__ ei) {
    int e = blockIdx.x * blockDim.x + threadIdx.x;
    if (e < EE) atomicAdd(&g_cnt[ei[e]], 1);
}

__global__ __launch_bounds__(1024) void k_scan() {
    __shared__ int part[1024];
    const int t = threadIdx.x;
    const int base = t * 10;
    int loc[10];
    int s = 0;
    #pragma unroll
    for (int i = 0; i < 10; i++) {
        int idx = base + i;
        int c = (idx < NN) ? g_cnt[idx] : 0;
        loc[i] = s; s += c;
    }
    part[t] = s;
    __syncthreads();
    for (int off = 1; off < 1024; off <<= 1) {
        int v = (t >= off) ? part[t - off] : 0;
        __syncthreads();
        part[t] += v;
        __syncthreads();
    }
    int pref = (t == 0) ? 0 : part[t - 1];
    #pragma unroll
    for (int i = 0; i < 10; i++) {
        int idx = base + i;
        if (idx < NN) g_rs[idx] = pref + loc[i];
    }
    if (t == 1023) g_rs[NN] = part[1023];
}

__global__ void k_scatter(const int* __restrict__ ei) {
    int e = blockIdx.x * blockDim.x + threadIdx.x;
    if (e < EE) {
        int d = ei[e];
        int pos = g_rs[d] + atomicAdd(&g_cur[d], 1);
        g_perm[pos] = e;
    }
}

// ---------------- aggregation: one block per node, pipelined, batched loads ----------------
__global__ __launch_bounds__(128) void k_agg(const int* __restrict__ ei,
                                             const float* __restrict__ ea) {
    const int n = blockIdx.x;
    const int u = threadIdx.x;
    const int beg = g_rs[n], end = g_rs[n + 1];
    float s0 = 0.f, s1 = 0.f;
    float v20 = 0.f, v21 = 0.f, v22 = 0.f;
    float v30 = 0.f, v31 = 0.f, v32 = 0.f;

    int e_c = 0, src_c = 0;
    float4 av_c = make_float4(0.f, 0.f, 0.f, 0.f);
    if (beg < end) {
        e_c = g_perm[beg];
        src_c = ei[EE + e_c];
        av_c = *reinterpret_cast<const float4*>(ea + (size_t)e_c * 4);
    }
    for (int i = beg; i < end; i++) {
        const int e = e_c, src = src_c;
        const float4 av = av_c;
        // front-batch all 8 independent global loads for this edge (MLP ~= 8)
        const float* wr = g_w + (size_t)e * 512;
        const float* yr = g_y + (size_t)src * 512;
        float wss = wr[u];
        float wsv = wr[128 + u];
        float wvs = wr[256 + u];
        float wvv = wr[384 + u];
        float ys  = yr[u];
        float yv0 = yr[128 + u];
        float yv1 = yr[256 + u];
        float yv2 = yr[384 + u];
        if (i + 1 < end) {                       // prefetch next edge's metadata
            e_c = g_perm[i + 1];
            src_c = ei[EE + e_c];
            av_c = *reinterpret_cast<const float4*>(ea + (size_t)e_c * 4);
        }
        float dv = yv0 * av.y + yv1 * av.z + yv2 * av.w;
        s0 += wss * ys * av.x;
        s1 += wvv * dv;
        float t = wsv * ys;
        v20 += t * av.y; v21 += t * av.z; v22 += t * av.w;
        float t2 = wvs * av.x;
        v30 += t2 * yv0; v31 += t2 * yv1; v32 += t2 * yv2;
    }
    const float inv = 0.25f;                       // 1/sqrt(16)
    const float isq3 = 0.5773502691896258f;        // 1/sqrt(3)
    float* a = g_acc + n * 1024;
    a[u]       = s0 * inv;
    a[128 + u] = s1 * inv * isq3;
    a[256 + u]       = v20 * inv;  a[256 + 128 + u] = v30 * inv;
    a[512 + u]       = v21 * inv;  a[512 + 128 + u] = v31 * inv;
    a[768 + u]       = v22 * inv;  a[768 + 128 + u] = v32 * inv;
}

// ---------------- sc einsum (writes out), GEMM K=1280 ----------------
__global__ __launch_bounds__(256) void k_sc(const float* __restrict__ nf,
                                            const float* __restrict__ na,
                                            const float* __restrict__ scs,
                                            const float* __restrict__ scv,
                                            float* __restrict__ out) {
    const int ch = blockIdx.z;
    const int n0 = blockIdx.x * 32;
    const float* W = (ch == 0) ? scs : scv;        // (128,10,128) flat u*1280+v*128+w
    __shared__ float sx[32][128];
    __shared__ float sat[32][10];
    __shared__ __align__(16) float sw[40][128];
    __shared__ float sa[32][40];
    const int tid = threadIdx.x;
    for (int idx = tid; idx < 32 * 128; idx += 256) {
        int m = idx >> 7, u = idx & 127;
        int n = n0 + m;
        float v = 0.f;
        if (n < NN) v = (ch == 0) ? nf[n * 512 + u] : nf[n * 512 + 128 + u * 3 + (ch - 1)];
        sx[m][u] = v;
    }
    for (int idx = tid; idx < 320; idx += 256) {
        int m = idx / 10, v = idx % 10;
        int n = n0 + m;
        sat[m][v] = (n < NN) ? na[n * 10 + v] : 0.f;
    }
    __syncthreads();
    const int tx = tid & 31, ty = tid >> 5;
    ull acc2[4][2] = {};                           // 4 rows x 2 packed pairs (4 cols)
    for (int u0 = 0; u0 < 128; u0 += 4) {
        for (int idx = tid; idx < 40 * 128; idx += 256) {
            int r = idx >> 7, w = idx & 127;
            sw[r][w] = W[(u0 + (r / 10)) * 1280 + (r % 10) * 128 + w];
        }
        for (int idx = tid; idx < 32 * 40; idx += 256) {
            int m = idx / 40, r = idx % 40;
            sa[m][r] = sx[m][u0 + r / 10] * sat[m][r % 10];
        }
        __syncthreads();
        #pragma unroll
        for (int r = 0; r < 40; r++) {
            const ull* bp = reinterpret_cast<const ull*>(&sw[r][tx * 4]);
            ull bb[2] = {bp[0], bp[1]};
            #pragma unroll
            for (int i = 0; i < 4; i++) {
                ull aa = pk2(sa[ty * 4 + i][r]);
                fma2(acc2[i][0], aa, bb[0]);
                fma2(acc2[i][1], aa, bb[1]);
            }
        }
        __syncthreads();
    }
    const float norm = 0.027950849718747371f;      // 1/sqrt(1280)
    #pragma unroll
    for (int i = 0; i < 4; i++) {
        int n = n0 + ty * 4 + i;
        if (n >= NN) continue;
        #pragma unroll
        for (int j = 0; j < 2; j++) {
            float2 p = up2(acc2[i][j]);
            int w = tx * 4 + j * 2;
            float v0 = p.x * norm, v1 = p.y * norm;
            if (ch == 0) { out[n * 512 + w] = v0; out[n * 512 + w + 1] = v1; }
            else {
                out[n * 512 + 128 + w * 3 + (ch - 1)]       = v0;
                out[n * 512 + 128 + (w + 1) * 3 + (ch - 1)] = v1;
            }
        }
    }
}

// ---------------- lin2: out += (s|v) @ W * 1/sqrt(256) ----------------
__global__ __launch_bounds__(256) void k_lin2(const float* __restrict__ ws,
                                              const float* __restrict__ wv,
                                              float* __restrict__ out) {
    const int ch = blockIdx.z;
    const int n0 = blockIdx.x * 32;
    const float* W = (ch == 0) ? ws : wv;          // (256,128)
    __shared__ float As[32][33];
    __shared__ __align__(16) float Bs[32][128];
    const int tid = threadIdx.x;
    const int tx = tid & 31, ty = tid >> 5;
    ull acc2[4][2] = {};
    for (int k0 = 0; k0 < 256; k0 += 32) {
        for (int idx = tid; idx < 32 * 32; idx += 256) {
            int m = idx >> 5, k = idx & 31;
            int n = n0 + m;
            As[m][k] = (n < NN) ? g_acc[n * 1024 + ch * 256 + k0 + k] : 0.f;
        }
        for (int idx = tid; idx < 32 * 128; idx += 256) {
            int k = idx >> 7, w = idx & 127;
            Bs[k][w] = W[(k0 + k) * 128 + w];
        }
        __syncthreads();
        #pragma unroll
        for (int k = 0; k < 32; k++) {
            const ull* bp = reinterpret_cast<const ull*>(&Bs[k][tx * 4]);
            ull bb[2] = {bp[0], bp[1]};
            #pragma unroll
            for (int i = 0; i < 4; i++) {
                ull aa = pk2(As[ty * 4 + i][k]);
                fma2(acc2[i][0], aa, bb[0]);
                fma2(acc2[i][1], aa, bb[1]);
            }
        }
        __syncthreads();
    }
    const float l2 = 0.0625f;                      // 1/sqrt(256)
    #pragma unroll
    for (int i = 0; i < 4; i++) {
        int n = n0 + ty * 4 + i;
        if (n >= NN) continue;
        #pragma unroll
        for (int j = 0; j < 2; j++) {
            float2 p = up2(acc2[i][j]);
            int w = tx * 4 + j * 2;
            float v0 = p.x * l2, v1 = p.y * l2;
            if (ch == 0) { out[n * 512 + w] += v0; out[n * 512 + w + 1] += v1; }
            else {
                out[n * 512 + 128 + w * 3 + (ch - 1)]       += v0;
                out[n * 512 + 128 + (w + 1) * 3 + (ch - 1)] += v1;
            }
        }
    }
}

// ---------------- launch ----------------
extern "C" void kernel_launch(void* const* d_in, const int* in_sizes, int n_in,
                              void* d_out, int out_size) {
    const float* nf  = (const float*)d_in[0];
    const float* na  = (const float*)d_in[1];
    const float* ef  = (const float*)d_in[2];
    const float* ea  = (const float*)d_in[3];
    const int*   ei  = (const int*)d_in[4];
    const float* l1s = (const float*)d_in[5];
    const float* l1v = (const float*)d_in[6];
    const float* w0  = (const float*)d_in[7];
    const float* w1  = (const float*)d_in[8];
    const float* w2  = (const float*)d_in[9];
    const float* l2s = (const float*)d_in[10];
    const float* l2v = (const float*)d_in[11];
    const float* scs = (const float*)d_in[12];
    const float* scv = (const float*)d_in[13];
    float* out = (float*)d_out;

    k_zero<<<(NN + 255) / 256, 256>>>();
    k_lin1<<<dim3((NN + 63) / 64, 1, 4), 256>>>(nf, l1s, l1v);
    k_mlp12<<<EE / 32, 256>>>(ef, w0, w1);
    k_mlp3<<<dim3(EE / 64, 4), 256>>>(w2);
    k_hist<<<(EE + 255) / 256, 256>>>(ei);
    k_scan<<<1, 1024>>>();
    k_scatter<<<(EE + 255) / 256, 256>>>(ei);
    k_agg<<<NN, 128>>>(ei, ea);
    k_sc<<<dim3((NN + 31) / 32, 1, 4), 256>>>(nf, na, scs, scv, out);
    k_lin2<<<dim3((NN + 31) / 32, 1, 4), 256>>>(l2s, l2v, out);
}

// round 10
// speedup vs baseline: 1.1772x; 1.1772x over previous
#include <cuda_runtime.h>
#include <math.h>

#define NN 10000
#define EE 160000

typedef unsigned long long ull;

// ---------------- packed f32x2 helpers (FFMA2 path, PTX-only) ----------------
__device__ __forceinline__ ull pk2(float x) {
    ull r; asm("mov.b64 %0, {%1, %1};" : "=l"(r) : "f"(x)); return r;
}
__device__ __forceinline__ void fma2(ull& d, ull a, ull b) {
    asm("fma.rn.f32x2 %0, %1, %2, %3;" : "=l"(d) : "l"(a), "l"(b), "l"(d));
}
__device__ __forceinline__ float2 up2(ull v) {
    float2 r; asm("mov.b64 {%0, %1}, %2;" : "=f"(r.x), "=f"(r.y) : "l"(v)); return r;
}

// ---------------- static scratch ----------------
__device__ float g_y[NN * 512];              // y_s at [n*512+w]; y_v[c] at [n*512+128+c*128+w]
__device__ float g_h[EE * 64];               // MLP hidden (after layer 2)
__device__ float g_w[(size_t)EE * 512];      // MLP output (ss|sv|vs|vv each 128)
__device__ float g_acc[NN * 1024];           // s(256) | v[c](256)x3
__device__ float g_za[(size_t)4 * NN * 1280];// expanded A for sc einsum, per channel
__device__ int   g_cnt[NN];
__device__ int   g_cur[NN];
__device__ int   g_rs[NN + 1];
__device__ int   g_perm[EE];

// ---------------- zero counters ----------------
__global__ void k_zero() {
    int i = blockIdx.x * blockDim.x + threadIdx.x;
    if (i < NN) { g_cnt[i] = 0; g_cur[i] = 0; }
}

// ---------------- lin1: y = x @ W * 1/sqrt(128) ----------------
__global__ __launch_bounds__(256) void k_lin1(const float* __restrict__ nf,
                                              const float* __restrict__ ws,
                                              const float* __restrict__ wv) {
    const int ch = blockIdx.z;            // 0: scalar, 1..3: vector channel
    const int m0 = blockIdx.x * 64;
    const float* W = (ch == 0) ? ws : wv;
    __shared__ float As[64][33];
    __shared__ __align__(16) float Bs[32][128];
    const int tid = threadIdx.x;
    const int tx = tid & 15, ty = tid >> 4;
    ull acc2[4][4] = {};
    for (int k0 = 0; k0 < 128; k0 += 32) {
        for (int idx = tid; idx < 64 * 32; idx += 256) {
            int m = idx >> 5, k = idx & 31;
            int n = m0 + m;
            float v = 0.f;
            if (n < NN) {
                int u = k0 + k;
                v = (ch == 0) ? nf[n * 512 + u] : nf[n * 512 + 128 + u * 3 + (ch - 1)];
            }
            As[m][k] = v;
        }
        for (int idx = tid; idx < 32 * 128; idx += 256) {
            int k = idx >> 7, w = idx & 127;
            Bs[k][w] = W[(k0 + k) * 128 + w];
        }
        __syncthreads();
        #pragma unroll 4
        for (int k = 0; k < 32; k++) {
            ull bb[4];
            #pragma unroll
            for (int j = 0; j < 4; j++)
                bb[j] = *reinterpret_cast<const ull*>(&Bs[k][tx * 2 + 32 * j]);
            #pragma unroll
            for (int i = 0; i < 4; i++) {
                ull aa = pk2(As[ty * 4 + i][k]);
                #pragma unroll
                for (int j = 0; j < 4; j++) fma2(acc2[i][j], aa, bb[j]);
            }
        }
        __syncthreads();
    }
    const float L1 = 0.08838834764831845f;   // 1/sqrt(128)
    #pragma unroll
    for (int i = 0; i < 4; i++) {
        int n = m0 + ty * 4 + i;
        if (n >= NN) continue;
        #pragma unroll
        for (int j = 0; j < 4; j++) {
            float2 p = up2(acc2[i][j]);
            int w = tx * 2 + 32 * j;
            float v0 = p.x * L1, v1 = p.y * L1;
            if (ch == 0) { g_y[n * 512 + w] = v0; g_y[n * 512 + w + 1] = v1; }
            else {
                g_y[n * 512 + 128 + (ch - 1) * 128 + w]     = v0;
                g_y[n * 512 + 128 + (ch - 1) * 128 + w + 1] = v1;
            }
        }
    }
}

// ---------------- edge MLP layers 1-2 ----------------
__global__ __launch_bounds__(256) void k_mlp12(const float* __restrict__ ef,
                                               const float* __restrict__ w0,
                                               const float* __restrict__ w1) {
    __shared__ float sw0[8 * 64];
    __shared__ float sw1[64 * 64];
    __shared__ float sef[32 * 8];
    __shared__ float sh1[32 * 64];
    const int tid = threadIdx.x;
    const int e0 = blockIdx.x * 32;
    for (int i = tid; i < 512; i += 256) sw0[i] = w0[i];
    for (int i = tid; i < 4096; i += 256) sw1[i] = w1[i];
    sef[tid] = ef[e0 * 8 + tid];
    __syncthreads();
    for (int idx = tid; idx < 2048; idx += 256) {
        int e = idx >> 6, j = idx & 63;
        float t = 0.f;
        #pragma unroll
        for (int k = 0; k < 8; k++) t += sef[e * 8 + k] * sw0[k * 64 + j];
        t *= 0.35355339059327373f;                       // 1/sqrt(8)
        sh1[idx] = 1.679f * t / (1.f + expf(-t));
    }
    __syncthreads();
    for (int idx = tid; idx < 2048; idx += 256) {
        int e = idx >> 6, j = idx & 63;
        float t = 0.f;
        #pragma unroll 8
        for (int k = 0; k < 64; k++) t += sh1[e * 64 + k] * sw1[k * 64 + j];
        t *= 0.125f;
        g_h[(e0 + e) * 64 + j] = 1.679f * t / (1.f + expf(-t));
    }
}

// ---------------- edge MLP layer 3: g_w = g_h @ w2 / 8 ----------------
// 128x128 tile, 8x8 outputs per thread (packed pairs along N)
__global__ __launch_bounds__(256) void k_mlp3(const float* __restrict__ w2) {
    const int e0 = blockIdx.x * 128;
    const int c0 = blockIdx.y * 128;
    __shared__ float As[128][33];
    __shared__ __align__(16) float Bs[32][128];
    const int tid = threadIdx.x;
    const int tx = tid & 15, ty = tid >> 4;
    ull acc2[8][4] = {};
    for (int k0 = 0; k0 < 64; k0 += 32) {
        for (int idx = tid; idx < 128 * 32; idx += 256) {
            int m = idx >> 5, k = idx & 31;
            As[m][k] = g_h[(e0 + m) * 64 + k0 + k];
        }
        for (int idx = tid; idx < 32 * 128; idx += 256) {
            int k = idx >> 7, w = idx & 127;
            Bs[k][w] = w2[(k0 + k) * 512 + c0 + w];
        }
        __syncthreads();
        #pragma unroll 4
        for (int k = 0; k < 32; k++) {
            ull bb[4];
            #pragma unroll
            for (int j = 0; j < 4; j++)
                bb[j] = *reinterpret_cast<const ull*>(&Bs[k][tx * 2 + 32 * j]);
            #pragma unroll
            for (int i = 0; i < 8; i++) {
                ull aa = pk2(As[ty * 8 + i][k]);
                #pragma unroll
                for (int j = 0; j < 4; j++) fma2(acc2[i][j], aa, bb[j]);
            }
        }
        __syncthreads();
    }
    #pragma unroll
    for (int i = 0; i < 8; i++) {
        size_t row = (size_t)(e0 + ty * 8 + i) * 512 + c0;
        #pragma unroll
        for (int j = 0; j < 4; j++) {
            float2 p = up2(acc2[i][j]);
            *reinterpret_cast<float2*>(&g_w[row + tx * 2 + 32 * j]) =
                make_float2(p.x * 0.125f, p.y * 0.125f);
        }
    }
}

// ---------------- CSR build ----------------
__global__ void k_hist(const int* __restrict__ ei) {
    int e = blockIdx.x * blockDim.x + threadIdx.x;
    if (e < EE) atomicAdd(&g_cnt[ei[e]], 1);
}

__global__ __launch_bounds__(1024) void k_scan() {
    __shared__ int part[1024];
    const int t = threadIdx.x;
    const int base = t * 10;
    int loc[10];
    int s = 0;
    #pragma unroll
    for (int i = 0; i < 10; i++) {
        int idx = base + i;
        int c = (idx < NN) ? g_cnt[idx] : 0;
        loc[i] = s; s += c;
    }
    part[t] = s;
    __syncthreads();
    for (int off = 1; off < 1024; off <<= 1) {
        int v = (t >= off) ? part[t - off] : 0;
        __syncthreads();
        part[t] += v;
        __syncthreads();
    }
    int pref = (t == 0) ? 0 : part[t - 1];
    #pragma unroll
    for (int i = 0; i < 10; i++) {
        int idx = base + i;
        if (idx < NN) g_rs[idx] = pref + loc[i];
    }
    if (t == 1023) g_rs[NN] = part[1023];
}

__global__ void k_scatter(const int* __restrict__ ei) {
    int e = blockIdx.x * blockDim.x + threadIdx.x;
    if (e < EE) {
        int d = ei[e];
        int pos = g_rs[d] + atomicAdd(&g_cur[d], 1);
        g_perm[pos] = e;
    }
}

// ---------------- aggregation: one block per node, pipelined, batched loads ----------------
__global__ __launch_bounds__(128) void k_agg(const int* __restrict__ ei,
                                             const float* __restrict__ ea) {
    const int n = blockIdx.x;
    const int u = threadIdx.x;
    const int beg = g_rs[n], end = g_rs[n + 1];
    float s0 = 0.f, s1 = 0.f;
    float v20 = 0.f, v21 = 0.f, v22 = 0.f;
    float v30 = 0.f, v31 = 0.f, v32 = 0.f;

    int e_c = 0, src_c = 0;
    float4 av_c = make_float4(0.f, 0.f, 0.f, 0.f);
    if (beg < end) {
        e_c = g_perm[beg];
        src_c = ei[EE + e_c];
        av_c = *reinterpret_cast<const float4*>(ea + (size_t)e_c * 4);
    }
    for (int i = beg; i < end; i++) {
        const int e = e_c, src = src_c;
        const float4 av = av_c;
        const float* wr = g_w + (size_t)e * 512;
        const float* yr = g_y + (size_t)src * 512;
        float wss = wr[u];
        float wsv = wr[128 + u];
        float wvs = wr[256 + u];
        float wvv = wr[384 + u];
        float ys  = yr[u];
        float yv0 = yr[128 + u];
        float yv1 = yr[256 + u];
        float yv2 = yr[384 + u];
        if (i + 1 < end) {
            e_c = g_perm[i + 1];
            src_c = ei[EE + e_c];
            av_c = *reinterpret_cast<const float4*>(ea + (size_t)e_c * 4);
        }
        float dv = yv0 * av.y + yv1 * av.z + yv2 * av.w;
        s0 += wss * ys * av.x;
        s1 += wvv * dv;
        float t = wsv * ys;
        v20 += t * av.y; v21 += t * av.z; v22 += t * av.w;
        float t2 = wvs * av.x;
        v30 += t2 * yv0; v31 += t2 * yv1; v32 += t2 * yv2;
    }
    const float inv = 0.25f;                       // 1/sqrt(16)
    const float isq3 = 0.5773502691896258f;        // 1/sqrt(3)
    float* a = g_acc + n * 1024;
    a[u]       = s0 * inv;
    a[128 + u] = s1 * inv * isq3;
    a[256 + u]       = v20 * inv;  a[256 + 128 + u] = v30 * inv;
    a[512 + u]       = v21 * inv;  a[512 + 128 + u] = v31 * inv;
    a[768 + u]       = v22 * inv;  a[768 + 128 + u] = v32 * inv;
}

// ---------------- expand A for sc einsum: za[ch][n][u*10+v] = x[ch][n][u]*attr[n][v] ----------------
__global__ __launch_bounds__(256) void k_expand(const float* __restrict__ nf,
                                                const float* __restrict__ na) {
    size_t idx = (size_t)blockIdx.x * 256 + threadIdx.x;
    if (idx >= (size_t)4 * NN * 1280) return;
    int r  = (int)(idx % 1280);
    int n  = (int)((idx / 1280) % NN);
    int ch = (int)(idx / ((size_t)NN * 1280));
    int u = r / 10, v = r % 10;
    float x = (ch == 0) ? nf[n * 512 + u] : nf[n * 512 + 128 + u * 3 + (ch - 1)];
    g_za[idx] = x * na[n * 10 + v];
}

// ---------------- sc einsum as plain GEMM: out = za @ W' * 1/sqrt(1280) ----------------
// M-tile 64, N 128, K 1280 in 32 tiles of 40; 4x8 outputs per thread
__global__ __launch_bounds__(256) void k_sc(const float* __restrict__ scs,
                                            const float* __restrict__ scv,
                                            float* __restrict__ out) {
    const int ch = blockIdx.z;
    const int n0 = blockIdx.x * 64;
    const float* W = (ch == 0) ? scs : scv;        // (128,10,128) flat u*1280+v*128+w
    const float* za = g_za + (size_t)ch * NN * 1280;
    __shared__ float sA[64][41];
    __shared__ __align__(16) float sw[40][128];
    const int tid = threadIdx.x;
    const int tx = tid & 15, ty = tid >> 4;
    ull acc2[4][4] = {};
    for (int t0 = 0; t0 < 32; t0++) {
        for (int idx = tid; idx < 64 * 40; idx += 256) {
            int m = idx / 40, r = idx % 40;
            int n = n0 + m;
            sA[m][r] = (n < NN) ? za[(size_t)n * 1280 + t0 * 40 + r] : 0.f;
        }
        for (int idx = tid; idx < 40 * 128; idx += 256) {
            int r = idx >> 7, w = idx & 127;
            int rg = t0 * 40 + r;
            sw[r][w] = W[(rg / 10) * 1280 + (rg % 10) * 128 + w];
        }
        __syncthreads();
        #pragma unroll 4
        for (int r = 0; r < 40; r++) {
            ull bb[4];
            #pragma unroll
            for (int j = 0; j < 4; j++)
                bb[j] = *reinterpret_cast<const ull*>(&sw[r][tx * 2 + 32 * j]);
            #pragma unroll
            for (int i = 0; i < 4; i++) {
                ull aa = pk2(sA[ty * 4 + i][r]);
                #pragma unroll
                for (int j = 0; j < 4; j++) fma2(acc2[i][j], aa, bb[j]);
            }
        }
        __syncthreads();
    }
    const float norm = 0.027950849718747371f;      // 1/sqrt(1280)
    #pragma unroll
    for (int i = 0; i < 4; i++) {
        int n = n0 + ty * 4 + i;
        if (n >= NN) continue;
        #pragma unroll
        for (int j = 0; j < 4; j++) {
            float2 p = up2(acc2[i][j]);
            int w = tx * 2 + 32 * j;
            float v0 = p.x * norm, v1 = p.y * norm;
            if (ch == 0) {
                *reinterpret_cast<float2*>(&out[n * 512 + w]) = make_float2(v0, v1);
            } else {
                out[n * 512 + 128 + w * 3 + (ch - 1)]       = v0;
                out[n * 512 + 128 + (w + 1) * 3 + (ch - 1)] = v1;
            }
        }
    }
}

// ---------------- lin2: out += (s|v) @ W * 1/sqrt(256) ----------------
__global__ __launch_bounds__(256) void k_lin2(const float* __restrict__ ws,
                                              const float* __restrict__ wv,
                                              float* __restrict__ out) {
    const int ch = blockIdx.z;
    const int n0 = blockIdx.x * 32;
    const float* W = (ch == 0) ? ws : wv;          // (256,128)
    __shared__ float As[32][33];
    __shared__ __align__(16) float Bs[32][128];
    const int tid = threadIdx.x;
    const int tx = tid & 15, ty = tid >> 4;
    ull acc2[2][4] = {};
    for (int k0 = 0; k0 < 256; k0 += 32) {
        for (int idx = tid; idx < 32 * 32; idx += 256) {
            int m = idx >> 5, k = idx & 31;
            int n = n0 + m;
            As[m][k] = (n < NN) ? g_acc[n * 1024 + ch * 256 + k0 + k] : 0.f;
        }
        for (int idx = tid; idx < 32 * 128; idx += 256) {
            int k = idx >> 7, w = idx & 127;
            Bs[k][w] = W[(k0 + k) * 128 + w];
        }
        __syncthreads();
        #pragma unroll 4
        for (int k = 0; k < 32; k++) {
            ull bb[4];
            #pragma unroll
            for (int j = 0; j < 4; j++)
                bb[j] = *reinterpret_cast<const ull*>(&Bs[k][tx * 2 + 32 * j]);
            #pragma unroll
            for (int i = 0; i < 2; i++) {
                ull aa = pk2(As[ty * 2 + i][k]);
                #pragma unroll
                for (int j = 0; j < 4; j++) fma2(acc2[i][j], aa, bb[j]);
            }
        }
        __syncthreads();
    }
    const float l2 = 0.0625f;                      // 1/sqrt(256)
    #pragma unroll
    for (int i = 0; i < 2; i++) {
        int n = n0 + ty * 2 + i;
        if (n >= NN) continue;
        #pragma unroll
        for (int j = 0; j < 4; j++) {
            float2 p = up2(acc2[i][j]);
            int w = tx * 2 + 32 * j;
            float v0 = p.x * l2, v1 = p.y * l2;
            if (ch == 0) { out[n * 512 + w] += v0; out[n * 512 + w + 1] += v1; }
            else {
                out[n * 512 + 128 + w * 3 + (ch - 1)]       += v0;
                out[n * 512 + 128 + (w + 1) * 3 + (ch - 1)] += v1;
            }
        }
    }
}

// ---------------- launch ----------------
extern "C" void kernel_launch(void* const* d_in, const int* in_sizes, int n_in,
                              void* d_out, int out_size) {
    const float* nf  = (const float*)d_in[0];
    const float* na  = (const float*)d_in[1];
    const float* ef  = (const float*)d_in[2];
    const float* ea  = (const float*)d_in[3];
    const int*   ei  = (const int*)d_in[4];
    const float* l1s = (const float*)d_in[5];
    const float* l1v = (const float*)d_in[6];
    const float* w0  = (const float*)d_in[7];
    const float* w1  = (const float*)d_in[8];
    const float* w2  = (const float*)d_in[9];
    const float* l2s = (const float*)d_in[10];
    const float* l2v = (const float*)d_in[11];
    const float* scs = (const float*)d_in[12];
    const float* scv = (const float*)d_in[13];
    float* out = (float*)d_out;

    k_zero<<<(NN + 255) / 256, 256>>>();
    k_lin1<<<dim3((NN + 63) / 64, 1, 4), 256>>>(nf, l1s, l1v);
    k_mlp12<<<EE / 32, 256>>>(ef, w0, w1);
    k_mlp3<<<dim3(EE / 128, 4), 256>>>(w2);
    k_hist<<<(EE + 255) / 256, 256>>>(ei);
    k_scan<<<1, 1024>>>();
    k_scatter<<<(EE + 255) / 256, 256>>>(ei);
    k_agg<<<NN, 128>>>(ei, ea);
    k_expand<<<(int)(((size_t)4 * NN * 1280 + 255) / 256), 256>>>(nf, na);
    k_sc<<<dim3((NN + 63) / 64, 1, 4), 256>>>(scs, scv, out);
    k_lin2<<<dim3((NN + 31) / 32, 1, 4), 256>>>(l2s, l2v, out);
}